// round 1
// baseline (speedup 1.0000x reference)
#include <cuda_runtime.h>
#include <cstdint>

#define BD 2
#define HD 64
#define WD 64
#define CD 256
#define GD 8
#define KP 9
#define HCD 32
#define PD (HD*WD)       // 4096
#define C3 (3*CD)        // 768
#define NO 160           // 153 outputs padded to 160
#define NF 768           // feature length for offset/mask GEMM

// ---------------- scratch (device globals; no allocation) ----------------
__device__ float g_qkv[BD*PD*C3];      // after qkv linear      (24 MB)
__device__ float g_qkvdw[BD*PD*C3];    // after depthwise conv  (24 MB)
__device__ float g_combW[NF*NO];       // folded offset/mask weights
__device__ float g_combB[NO];          // folded biases (incl. base grid)
__device__ float g_offmask[BD*PD*NO];  // per-pixel 144 offsets + 9 masks
__device__ float g_attout[BD*PD*CD];   // attention output before proj

__constant__ float c_PTS[18] = {-1,-1,-1,0,-1,1,0,-1,0,0,0,1,1,-1,1,0,1,1};

// ---------------- generic SGEMM: C = A[MxK] * B[KxN] + bias --------------
// BM=128, BN=64, BK=16, 256 threads, 8x4 register tile.
// Requires M%128==0, N%64==0, K%16==0, rows 16B-aligned (true here).
__global__ void __launch_bounds__(256) sgemm_bias_kernel(
    const float* __restrict__ A, const float* __restrict__ B,
    const float* __restrict__ bias, float* __restrict__ C,
    int M, int N, int K)
{
    const int BM = 128, BN = 64, BK = 16;
    __shared__ float As[BK][BM];
    __shared__ float Bs[BK][BN];
    int tid = threadIdx.x;
    int tx = tid & 15;    // N direction, 4 cols each
    int ty = tid >> 4;    // M direction, 8 rows each
    int row0 = blockIdx.y * BM;
    int col0 = blockIdx.x * BN;

    float acc[8][4];
#pragma unroll
    for (int i = 0; i < 8; i++)
#pragma unroll
        for (int j = 0; j < 4; j++) acc[i][j] = 0.f;

    for (int k0 = 0; k0 < K; k0 += BK) {
        // A tile: 128x16 -> 512 float4 along K, 2 per thread (stored transposed)
#pragma unroll
        for (int i = 0; i < 2; i++) {
            int e = tid + i * 256;
            int m = e >> 2;
            int kk = (e & 3) << 2;
            float4 v = *reinterpret_cast<const float4*>(&A[(size_t)(row0 + m) * K + k0 + kk]);
            As[kk + 0][m] = v.x; As[kk + 1][m] = v.y;
            As[kk + 2][m] = v.z; As[kk + 3][m] = v.w;
        }
        // B tile: 16x64 -> 256 float4 along N, 1 per thread
        {
            int kk = tid >> 4;
            int n4 = (tid & 15) << 2;
            *reinterpret_cast<float4*>(&Bs[kk][n4]) =
                *reinterpret_cast<const float4*>(&B[(size_t)(k0 + kk) * N + col0 + n4]);
        }
        __syncthreads();
#pragma unroll
        for (int k = 0; k < BK; k++) {
            float a[8], bb[4];
            float4 a0 = *reinterpret_cast<const float4*>(&As[k][ty * 8]);
            float4 a1 = *reinterpret_cast<const float4*>(&As[k][ty * 8 + 4]);
            a[0] = a0.x; a[1] = a0.y; a[2] = a0.z; a[3] = a0.w;
            a[4] = a1.x; a[5] = a1.y; a[6] = a1.z; a[7] = a1.w;
            float4 b0 = *reinterpret_cast<const float4*>(&Bs[k][tx * 4]);
            bb[0] = b0.x; bb[1] = b0.y; bb[2] = b0.z; bb[3] = b0.w;
#pragma unroll
            for (int i = 0; i < 8; i++)
#pragma unroll
                for (int j = 0; j < 4; j++)
                    acc[i][j] += a[i] * bb[j];
        }
        __syncthreads();
    }
    float4 bv = *reinterpret_cast<const float4*>(&bias[col0 + tx * 4]);
#pragma unroll
    for (int i = 0; i < 8; i++) {
        int m = row0 + ty * 8 + i;
        float4 o;
        o.x = acc[i][0] + bv.x; o.y = acc[i][1] + bv.y;
        o.z = acc[i][2] + bv.z; o.w = acc[i][3] + bv.w;
        *reinterpret_cast<float4*>(&C[(size_t)m * N + col0 + tx * 4]) = o;
    }
}

// ---------------- depthwise 3x3 conv, NHWC, SAME zero pad ----------------
__global__ void __launch_bounds__(192) dwconv_kernel(
    const float* __restrict__ in, const float* __restrict__ w,
    const float* __restrict__ bias, float* __restrict__ out)
{
    int c = threadIdx.x * 4;               // 0..764
    int x = blockIdx.x, y = blockIdx.y, b = blockIdx.z;
    float4 acc = *reinterpret_cast<const float4*>(&bias[c]);
#pragma unroll
    for (int ky = 0; ky < 3; ky++) {
        int yy = y + ky - 1;
        if (yy < 0 || yy >= HD) continue;
#pragma unroll
        for (int kx = 0; kx < 3; kx++) {
            int xx = x + kx - 1;
            if (xx < 0 || xx >= WD) continue;
            float4 wv = *reinterpret_cast<const float4*>(&w[(ky * 3 + kx) * C3 + c]);
            float4 iv = *reinterpret_cast<const float4*>(
                &in[(size_t)((b * HD + yy) * WD + xx) * C3 + c]);
            acc.x += wv.x * iv.x; acc.y += wv.y * iv.y;
            acc.z += wv.z * iv.z; acc.w += wv.w * iv.w;
        }
    }
    *reinterpret_cast<float4*>(&out[(size_t)((b * HD + y) * WD + x) * C3 + c]) = acc;
}

// ---------------- fold pconv+proj weights into combW/combB ----------------
// off_pconv_w [8][64][64][3][3], off_w [8][18][256], off_b [8][18]
// mask_pconv_w [64][64][3][3],   mask_w [9][256],    mask_b [9]
// feature f: f<576 -> tap t=f/64, in-ch ic=f%64 ; f>=576 -> center ch f-512
__global__ void prep_kernel(
    const float* __restrict__ off_pconv_w, const float* __restrict__ off_w,
    const float* __restrict__ off_b, const float* __restrict__ mask_pconv_w,
    const float* __restrict__ mask_w, const float* __restrict__ mask_b)
{
    int o = blockIdx.x;        // 0..159
    int tid = threadIdx.x;     // 128
    if (o >= 153) {
        for (int f = tid; f < NF; f += 128) g_combW[f * NO + o] = 0.f;
        if (tid == 0) g_combB[o] = 0.f;
        return;
    }
    bool is_mask = (o >= 144);
    int g = 0, j = 0, kk = 0;
    if (!is_mask) { g = o / 18; j = o % 18; } else { kk = o - 144; }

    for (int f = tid; f < NF; f += 128) {
        float s;
        if (f < 576) {
            int t = f >> 6;
            int ic = f & 63;
            s = 0.f;
            if (!is_mask) {
                const float* ow = off_w + (g * 18 + j) * 256;
                const float* pc = off_pconv_w + ((size_t)(g * 64) * 64 + ic) * 9 + t;
                for (int oc = 0; oc < 64; oc++)
                    s += ow[oc] * pc[(size_t)oc * 64 * 9];
            } else {
                const float* mw = mask_w + kk * 256;
                const float* pc = mask_pconv_w + (size_t)ic * 9 + t;
                for (int oc = 0; oc < 64; oc++)
                    s += mw[oc] * pc[(size_t)oc * 64 * 9];
            }
        } else {
            int ch = f - 512;   // 64..255
            s = is_mask ? mask_w[kk * 256 + ch] : off_w[(g * 18 + j) * 256 + ch];
        }
        g_combW[f * NO + o] = s;
    }
    if (tid == 0) {
        g_combB[o] = is_mask ? mask_b[kk]
                             : (off_b[g * 18 + j] + c_PTS[j] * (float)(2 * g + 1));
    }
}

// ---------------- offset/mask GEMM: per image row, 64px x 160 x 768 -------
__global__ void __launch_bounds__(256) offmask_kernel(const float* __restrict__ qkvdw)
{
    int bh = blockIdx.x;            // 0..127
    int b = bh / HD, h = bh % HD;
    __shared__ float As[32][68];    // [k][px]  (pad 68 keeps 16B alignment)
    __shared__ float Bs[32][NO];    // [k][o]
    int tid = threadIdx.x;
    int tx = tid & 31;              // 5 output cols: tx*5 ..
    int ty = tid >> 5;              // 8 pixel rows: ty*8 ..

    float acc[8][5];
#pragma unroll
    for (int i = 0; i < 8; i++)
#pragma unroll
        for (int j = 0; j < 5; j++) acc[i][j] = 0.f;

    const float* qrow = qkvdw + (size_t)(b * HD + h) * WD * C3;

    for (int kc = 0; kc < NF; kc += 32) {
        // fill A chunk: 32 features x 64 pixels (gathered, zero-padded)
#pragma unroll
        for (int i = 0; i < 8; i++) {
            int e = tid + i * 256;      // 0..2047
            int kkk = e >> 6;
            int px = e & 63;
            int f = kc + kkk;
            float val;
            if (f < 576) {
                int t = f >> 6, c = f & 63;
                int yy = h + t / 3 - 1;
                int xx = px + t % 3 - 1;
                val = (yy >= 0 && yy < HD && xx >= 0 && xx < WD)
                    ? qkvdw[(size_t)((b * HD + yy) * WD + xx) * C3 + c] : 0.f;
            } else {
                val = qrow[(size_t)px * C3 + (f - 512)];
            }
            As[kkk][px] = val;
        }
        // fill B chunk: 32 x 160 = 1280 float4 slots, 5 per thread
#pragma unroll
        for (int i = 0; i < 5; i++) {
            int e = tid + i * 256;
            int kkk = e / 40;
            int n4 = (e % 40) * 4;
            *reinterpret_cast<float4*>(&Bs[kkk][n4]) =
                *reinterpret_cast<const float4*>(&g_combW[(size_t)(kc + kkk) * NO + n4]);
        }
        __syncthreads();
#pragma unroll
        for (int k = 0; k < 32; k++) {
            float a[8];
            float4 a0 = *reinterpret_cast<const float4*>(&As[k][ty * 8]);
            float4 a1 = *reinterpret_cast<const float4*>(&As[k][ty * 8 + 4]);
            a[0] = a0.x; a[1] = a0.y; a[2] = a0.z; a[3] = a0.w;
            a[4] = a1.x; a[5] = a1.y; a[6] = a1.z; a[7] = a1.w;
            float bb[5];
#pragma unroll
            for (int j = 0; j < 5; j++) bb[j] = Bs[k][tx * 5 + j];
#pragma unroll
            for (int i = 0; i < 8; i++)
#pragma unroll
                for (int j = 0; j < 5; j++)
                    acc[i][j] += a[i] * bb[j];
        }
        __syncthreads();
    }
#pragma unroll
    for (int i = 0; i < 8; i++) {
        int px = ty * 8 + i;
        size_t base = ((size_t)(b * HD + h) * WD + px) * NO;
#pragma unroll
        for (int j = 0; j < 5; j++) {
            int o = tx * 5 + j;
            g_offmask[base + o] = acc[i][j] + g_combB[o];
        }
    }
}

// ---------------- deformable attention: warp per (b,g,pixel) --------------
__global__ void __launch_bounds__(256) attn_kernel(const float* __restrict__ qkvdw)
{
    int warp = threadIdx.x >> 5;
    int lane = threadIdx.x & 31;
    int px = blockIdx.x * 8 + warp;     // 0..4095
    int g = blockIdx.y;
    int b = blockIdx.z;
    int h = px >> 6, w = px & 63;

    const float* om = g_offmask + ((size_t)(b * HD + h) * WD + w) * NO;
    size_t pixbase = (size_t)((b * HD + h) * WD + w) * C3;
    float qv = qkvdw[pixbase + g * HCD + lane] * 0.17677669529663687f; // 32^-0.5

    float attn[KP], vk[KP];
#pragma unroll
    for (int k = 0; k < KP; k++) {
        float ox = om[g * 18 + 2 * k];
        float oy = om[g * 18 + 2 * k + 1];
        float mk = om[144 + k];
        float cx = fminf(fmaxf((float)w + ox, 0.f), (float)(WD - 1));
        float cy = fminf(fmaxf((float)h + oy, 0.f), (float)(HD - 1));
        float x0f = floorf(cx), y0f = floorf(cy);
        float fx = cx - x0f, fy = cy - y0f;
        int x0 = (int)x0f, y0 = (int)y0f;
        int x1 = min(x0 + 1, WD - 1), y1 = min(y0 + 1, HD - 1);
        size_t i00 = (size_t)((b * HD + y0) * WD + x0) * C3 + CD + g * HCD + lane;
        size_t i01 = (size_t)((b * HD + y0) * WD + x1) * C3 + CD + g * HCD + lane;
        size_t i10 = (size_t)((b * HD + y1) * WD + x0) * C3 + CD + g * HCD + lane;
        size_t i11 = (size_t)((b * HD + y1) * WD + x1) * C3 + CD + g * HCD + lane;
        float w00 = (1.f - fx) * (1.f - fy), w01 = fx * (1.f - fy);
        float w10 = (1.f - fx) * fy,         w11 = fx * fy;
        float kvv = qkvdw[i00] * w00 + qkvdw[i01] * w01
                  + qkvdw[i10] * w10 + qkvdw[i11] * w11;
        float vvv = qkvdw[i00 + CD] * w00 + qkvdw[i01 + CD] * w01
                  + qkvdw[i10 + CD] * w10 + qkvdw[i11 + CD] * w11;
        kvv *= mk; vvv *= mk;
        float d = qv * kvv;
#pragma unroll
        for (int s = 16; s; s >>= 1) d += __shfl_xor_sync(0xffffffffu, d, s);
        attn[k] = d;
        vk[k] = vvv;
    }
    float m = attn[0];
#pragma unroll
    for (int k = 1; k < KP; k++) m = fmaxf(m, attn[k]);
    float ssum = 0.f, o = 0.f;
#pragma unroll
    for (int k = 0; k < KP; k++) {
        float e = __expf(attn[k] - m);
        ssum += e;
        o += e * vk[k];
    }
    o /= ssum;
    g_attout[((size_t)((b * HD + h) * WD + w)) * CD + g * HCD + lane] = o;
}

// --------------------------------- launch ---------------------------------
extern "C" void kernel_launch(void* const* d_in, const int* in_sizes, int n_in,
                              void* d_out, int out_size)
{
    const float* x            = (const float*)d_in[0];
    const float* qkv_w        = (const float*)d_in[1];
    const float* qkv_b        = (const float*)d_in[2];
    const float* dw_w         = (const float*)d_in[3];
    const float* dw_b         = (const float*)d_in[4];
    const float* off_pconv_w  = (const float*)d_in[5];
    const float* off_w        = (const float*)d_in[6];
    const float* off_b        = (const float*)d_in[7];
    const float* mask_pconv_w = (const float*)d_in[8];
    const float* mask_w       = (const float*)d_in[9];
    const float* mask_b       = (const float*)d_in[10];
    const float* proj_w       = (const float*)d_in[11];
    const float* proj_b       = (const float*)d_in[12];
    float* out = (float*)d_out;

    float *qkv, *qkvdw, *attout;
    cudaGetSymbolAddress((void**)&qkv, g_qkv);
    cudaGetSymbolAddress((void**)&qkvdw, g_qkvdw);
    cudaGetSymbolAddress((void**)&attout, g_attout);

    // 1) qkv = x @ qkv_w + qkv_b : [8192,256]x[256,768]
    {
        dim3 grid(C3 / 64, (BD * PD) / 128);
        sgemm_bias_kernel<<<grid, 256>>>(x, qkv_w, qkv_b, qkv, BD * PD, C3, CD);
    }
    // 2) depthwise 3x3 + bias
    {
        dim3 grid(WD, HD, BD);
        dwconv_kernel<<<grid, 192>>>(qkv, dw_w, dw_b, qkvdw);
    }
    // 3) fold offset/mask weights
    prep_kernel<<<NO, 128>>>(off_pconv_w, off_w, off_b, mask_pconv_w, mask_w, mask_b);
    // 4) offsets + masks for every pixel
    offmask_kernel<<<BD * HD, 256>>>(qkvdw);
    // 5) deformable attention
    {
        dim3 grid(PD / 8, GD, BD);
        attn_kernel<<<grid, 256>>>(qkvdw);
    }
    // 6) out = attout @ proj_w + proj_b : [8192,256]x[256,256]
    {
        dim3 grid(CD / 64, (BD * PD) / 128);
        sgemm_bias_kernel<<<grid, 256>>>(attout, proj_w, proj_b, out, BD * PD, CD, CD);
    }
}

// round 2
// speedup vs baseline: 1.0017x; 1.0017x over previous
#include <cuda_runtime.h>
#include <cstdint>

#define BD 2
#define HD 64
#define WD 64
#define CD 256
#define GD 8
#define KP 9
#define HCD 32
#define PD (HD*WD)       // 4096
#define C3 (3*CD)        // 768
#define NO 160           // 153 outputs padded to 160
#define NF 768           // feature length for offset/mask GEMM

// ---------------- scratch (device globals; no allocation) ----------------
__device__ float g_qkv[BD*PD*C3];      // after qkv linear      (24 MB)
__device__ float g_qkvdw[BD*PD*C3];    // after depthwise conv  (24 MB)
__device__ float g_combW[NF*NO];       // folded offset/mask weights
__device__ float g_combB[NO];          // folded biases (incl. base grid)
__device__ float g_offmask[BD*PD*NO];  // per-pixel 144 offsets + 9 masks
__device__ float g_attout[BD*PD*CD];   // attention output before proj

__constant__ float c_PTS[18] = {-1,-1,-1,0,-1,1,0,-1,0,0,0,1,1,-1,1,0,1,1};

// ---------------- generic SGEMM: C = A[MxK] * B[KxN] + bias --------------
// BM=128, BN=64, BK=16, 256 threads, 8x4 register tile.
// Requires M%128==0, N%64==0, K%16==0, rows 16B-aligned (true here).
__global__ void __launch_bounds__(256) sgemm_bias_kernel(
    const float* __restrict__ A, const float* __restrict__ B,
    const float* __restrict__ bias, float* __restrict__ C,
    int M, int N, int K)
{
    const int BM = 128, BN = 64, BK = 16;
    __shared__ float As[BK][BM];
    __shared__ float Bs[BK][BN];
    int tid = threadIdx.x;
    int tx = tid & 15;    // N direction, 4 cols each
    int ty = tid >> 4;    // M direction, 8 rows each
    int row0 = blockIdx.y * BM;
    int col0 = blockIdx.x * BN;

    float acc[8][4];
#pragma unroll
    for (int i = 0; i < 8; i++)
#pragma unroll
        for (int j = 0; j < 4; j++) acc[i][j] = 0.f;

    for (int k0 = 0; k0 < K; k0 += BK) {
        // A tile: 128x16 -> 512 float4 along K, 2 per thread (stored transposed)
#pragma unroll
        for (int i = 0; i < 2; i++) {
            int e = tid + i * 256;
            int m = e >> 2;
            int kk = (e & 3) << 2;
            float4 v = *reinterpret_cast<const float4*>(&A[(size_t)(row0 + m) * K + k0 + kk]);
            As[kk + 0][m] = v.x; As[kk + 1][m] = v.y;
            As[kk + 2][m] = v.z; As[kk + 3][m] = v.w;
        }
        // B tile: 16x64 -> 256 float4 along N, 1 per thread
        {
            int kk = tid >> 4;
            int n4 = (tid & 15) << 2;
            *reinterpret_cast<float4*>(&Bs[kk][n4]) =
                *reinterpret_cast<const float4*>(&B[(size_t)(k0 + kk) * N + col0 + n4]);
        }
        __syncthreads();
#pragma unroll
        for (int k = 0; k < BK; k++) {
            float a[8], bb[4];
            float4 a0 = *reinterpret_cast<const float4*>(&As[k][ty * 8]);
            float4 a1 = *reinterpret_cast<const float4*>(&As[k][ty * 8 + 4]);
            a[0] = a0.x; a[1] = a0.y; a[2] = a0.z; a[3] = a0.w;
            a[4] = a1.x; a[5] = a1.y; a[6] = a1.z; a[7] = a1.w;
            float4 b0 = *reinterpret_cast<const float4*>(&Bs[k][tx * 4]);
            bb[0] = b0.x; bb[1] = b0.y; bb[2] = b0.z; bb[3] = b0.w;
#pragma unroll
            for (int i = 0; i < 8; i++)
#pragma unroll
                for (int j = 0; j < 4; j++)
                    acc[i][j] += a[i] * bb[j];
        }
        __syncthreads();
    }
    float4 bv = *reinterpret_cast<const float4*>(&bias[col0 + tx * 4]);
#pragma unroll
    for (int i = 0; i < 8; i++) {
        int m = row0 + ty * 8 + i;
        float4 o;
        o.x = acc[i][0] + bv.x; o.y = acc[i][1] + bv.y;
        o.z = acc[i][2] + bv.z; o.w = acc[i][3] + bv.w;
        *reinterpret_cast<float4*>(&C[(size_t)m * N + col0 + tx * 4]) = o;
    }
}

// ---------------- depthwise 3x3 conv, NHWC, SAME zero pad ----------------
__global__ void __launch_bounds__(192) dwconv_kernel(
    const float* __restrict__ in, const float* __restrict__ w,
    const float* __restrict__ bias, float* __restrict__ out)
{
    int c = threadIdx.x * 4;               // 0..764
    int x = blockIdx.x, y = blockIdx.y, b = blockIdx.z;
    float4 acc = *reinterpret_cast<const float4*>(&bias[c]);
#pragma unroll
    for (int ky = 0; ky < 3; ky++) {
        int yy = y + ky - 1;
        if (yy < 0 || yy >= HD) continue;
#pragma unroll
        for (int kx = 0; kx < 3; kx++) {
            int xx = x + kx - 1;
            if (xx < 0 || xx >= WD) continue;
            float4 wv = *reinterpret_cast<const float4*>(&w[(ky * 3 + kx) * C3 + c]);
            float4 iv = *reinterpret_cast<const float4*>(
                &in[(size_t)((b * HD + yy) * WD + xx) * C3 + c]);
            acc.x += wv.x * iv.x; acc.y += wv.y * iv.y;
            acc.z += wv.z * iv.z; acc.w += wv.w * iv.w;
        }
    }
    *reinterpret_cast<float4*>(&out[(size_t)((b * HD + y) * WD + x) * C3 + c]) = acc;
}

// ---------------- fold pconv+proj weights into combW/combB ----------------
// off_pconv_w [8][64][64][3][3], off_w [8][18][256], off_b [8][18]
// mask_pconv_w [64][64][3][3],   mask_w [9][256],    mask_b [9]
// feature f: f<576 -> tap t=f/64, in-ch ic=f%64 ; f>=576 -> center ch f-512
__global__ void prep_kernel(
    const float* __restrict__ off_pconv_w, const float* __restrict__ off_w,
    const float* __restrict__ off_b, const float* __restrict__ mask_pconv_w,
    const float* __restrict__ mask_w, const float* __restrict__ mask_b)
{
    int o = blockIdx.x;        // 0..159
    int tid = threadIdx.x;     // 128
    if (o >= 153) {
        for (int f = tid; f < NF; f += 128) g_combW[f * NO + o] = 0.f;
        if (tid == 0) g_combB[o] = 0.f;
        return;
    }
    bool is_mask = (o >= 144);
    int g = 0, j = 0, kk = 0;
    if (!is_mask) { g = o / 18; j = o % 18; } else { kk = o - 144; }

    for (int f = tid; f < NF; f += 128) {
        float s;
        if (f < 576) {
            int t = f >> 6;
            int ic = f & 63;
            s = 0.f;
            if (!is_mask) {
                const float* ow = off_w + (g * 18 + j) * 256;
                const float* pc = off_pconv_w + ((size_t)(g * 64) * 64 + ic) * 9 + t;
                for (int oc = 0; oc < 64; oc++)
                    s += ow[oc] * pc[(size_t)oc * 64 * 9];
            } else {
                const float* mw = mask_w + kk * 256;
                const float* pc = mask_pconv_w + (size_t)ic * 9 + t;
                for (int oc = 0; oc < 64; oc++)
                    s += mw[oc] * pc[(size_t)oc * 64 * 9];
            }
        } else {
            int ch = f - 512;   // 64..255
            s = is_mask ? mask_w[kk * 256 + ch] : off_w[(g * 18 + j) * 256 + ch];
        }
        g_combW[f * NO + o] = s;
    }
    if (tid == 0) {
        g_combB[o] = is_mask ? mask_b[kk]
                             : (off_b[g * 18 + j] + c_PTS[j] * (float)(2 * g + 1));
    }
}

// ---------------- offset/mask GEMM: per image row, 64px x 160 x 768 -------
__global__ void __launch_bounds__(256) offmask_kernel(const float* __restrict__ qkvdw)
{
    int bh = blockIdx.x;            // 0..127
    int b = bh / HD, h = bh % HD;
    __shared__ float As[32][68];    // [k][px]  (pad 68 keeps 16B alignment)
    __shared__ float Bs[32][NO];    // [k][o]
    int tid = threadIdx.x;
    int tx = tid & 31;              // 5 output cols: tx*5 ..
    int ty = tid >> 5;              // 8 pixel rows: ty*8 ..

    float acc[8][5];
#pragma unroll
    for (int i = 0; i < 8; i++)
#pragma unroll
        for (int j = 0; j < 5; j++) acc[i][j] = 0.f;

    const float* qrow = qkvdw + (size_t)(b * HD + h) * WD * C3;

    for (int kc = 0; kc < NF; kc += 32) {
        // fill A chunk: 32 features x 64 pixels (gathered, zero-padded)
#pragma unroll
        for (int i = 0; i < 8; i++) {
            int e = tid + i * 256;      // 0..2047
            int kkk = e >> 6;
            int px = e & 63;
            int f = kc + kkk;
            float val;
            if (f < 576) {
                int t = f >> 6, c = f & 63;
                int yy = h + t / 3 - 1;
                int xx = px + t % 3 - 1;
                val = (yy >= 0 && yy < HD && xx >= 0 && xx < WD)
                    ? qkvdw[(size_t)((b * HD + yy) * WD + xx) * C3 + c] : 0.f;
            } else {
                val = qrow[(size_t)px * C3 + (f - 512)];
            }
            As[kkk][px] = val;
        }
        // fill B chunk: 32 x 160 = 1280 float4 slots, 5 per thread
#pragma unroll
        for (int i = 0; i < 5; i++) {
            int e = tid + i * 256;
            int kkk = e / 40;
            int n4 = (e % 40) * 4;
            *reinterpret_cast<float4*>(&Bs[kkk][n4]) =
                *reinterpret_cast<const float4*>(&g_combW[(size_t)(kc + kkk) * NO + n4]);
        }
        __syncthreads();
#pragma unroll
        for (int k = 0; k < 32; k++) {
            float a[8];
            float4 a0 = *reinterpret_cast<const float4*>(&As[k][ty * 8]);
            float4 a1 = *reinterpret_cast<const float4*>(&As[k][ty * 8 + 4]);
            a[0] = a0.x; a[1] = a0.y; a[2] = a0.z; a[3] = a0.w;
            a[4] = a1.x; a[5] = a1.y; a[6] = a1.z; a[7] = a1.w;
            float bb[5];
#pragma unroll
            for (int j = 0; j < 5; j++) bb[j] = Bs[k][tx * 5 + j];
#pragma unroll
            for (int i = 0; i < 8; i++)
#pragma unroll
                for (int j = 0; j < 5; j++)
                    acc[i][j] += a[i] * bb[j];
        }
        __syncthreads();
    }
#pragma unroll
    for (int i = 0; i < 8; i++) {
        int px = ty * 8 + i;
        size_t base = ((size_t)(b * HD + h) * WD + px) * NO;
#pragma unroll
        for (int j = 0; j < 5; j++) {
            int o = tx * 5 + j;
            g_offmask[base + o] = acc[i][j] + g_combB[o];
        }
    }
}

// ---------------- deformable attention: warp per (b,g,pixel) --------------
__global__ void __launch_bounds__(256) attn_kernel(const float* __restrict__ qkvdw)
{
    int warp = threadIdx.x >> 5;
    int lane = threadIdx.x & 31;
    int px = blockIdx.x * 8 + warp;     // 0..4095
    int g = blockIdx.y;
    int b = blockIdx.z;
    int h = px >> 6, w = px & 63;

    const float* om = g_offmask + ((size_t)(b * HD + h) * WD + w) * NO;
    size_t pixbase = (size_t)((b * HD + h) * WD + w) * C3;
    float qv = qkvdw[pixbase + g * HCD + lane] * 0.17677669529663687f; // 32^-0.5

    float attn[KP], vk[KP];
#pragma unroll
    for (int k = 0; k < KP; k++) {
        float ox = om[g * 18 + 2 * k];
        float oy = om[g * 18 + 2 * k + 1];
        float mk = om[144 + k];
        float cx = fminf(fmaxf((float)w + ox, 0.f), (float)(WD - 1));
        float cy = fminf(fmaxf((float)h + oy, 0.f), (float)(HD - 1));
        float x0f = floorf(cx), y0f = floorf(cy);
        float fx = cx - x0f, fy = cy - y0f;
        int x0 = (int)x0f, y0 = (int)y0f;
        int x1 = min(x0 + 1, WD - 1), y1 = min(y0 + 1, HD - 1);
        size_t i00 = (size_t)((b * HD + y0) * WD + x0) * C3 + CD + g * HCD + lane;
        size_t i01 = (size_t)((b * HD + y0) * WD + x1) * C3 + CD + g * HCD + lane;
        size_t i10 = (size_t)((b * HD + y1) * WD + x0) * C3 + CD + g * HCD + lane;
        size_t i11 = (size_t)((b * HD + y1) * WD + x1) * C3 + CD + g * HCD + lane;
        float w00 = (1.f - fx) * (1.f - fy), w01 = fx * (1.f - fy);
        float w10 = (1.f - fx) * fy,         w11 = fx * fy;
        float kvv = qkvdw[i00] * w00 + qkvdw[i01] * w01
                  + qkvdw[i10] * w10 + qkvdw[i11] * w11;
        float vvv = qkvdw[i00 + CD] * w00 + qkvdw[i01 + CD] * w01
                  + qkvdw[i10 + CD] * w10 + qkvdw[i11 + CD] * w11;
        kvv *= mk; vvv *= mk;
        float d = qv * kvv;
#pragma unroll
        for (int s = 16; s; s >>= 1) d += __shfl_xor_sync(0xffffffffu, d, s);
        attn[k] = d;
        vk[k] = vvv;
    }
    float m = attn[0];
#pragma unroll
    for (int k = 1; k < KP; k++) m = fmaxf(m, attn[k]);
    float ssum = 0.f, o = 0.f;
#pragma unroll
    for (int k = 0; k < KP; k++) {
        float e = __expf(attn[k] - m);
        ssum += e;
        o += e * vk[k];
    }
    o /= ssum;
    g_attout[((size_t)((b * HD + h) * WD + w)) * CD + g * HCD + lane] = o;
}

// --------------------------------- launch ---------------------------------
extern "C" void kernel_launch(void* const* d_in, const int* in_sizes, int n_in,
                              void* d_out, int out_size)
{
    const float* x            = (const float*)d_in[0];
    const float* qkv_w        = (const float*)d_in[1];
    const float* qkv_b        = (const float*)d_in[2];
    const float* dw_w         = (const float*)d_in[3];
    const float* dw_b         = (const float*)d_in[4];
    const float* off_pconv_w  = (const float*)d_in[5];
    const float* off_w        = (const float*)d_in[6];
    const float* off_b        = (const float*)d_in[7];
    const float* mask_pconv_w = (const float*)d_in[8];
    const float* mask_w       = (const float*)d_in[9];
    const float* mask_b       = (const float*)d_in[10];
    const float* proj_w       = (const float*)d_in[11];
    const float* proj_b       = (const float*)d_in[12];
    float* out = (float*)d_out;

    float *qkv, *qkvdw, *attout;
    cudaGetSymbolAddress((void**)&qkv, g_qkv);
    cudaGetSymbolAddress((void**)&qkvdw, g_qkvdw);
    cudaGetSymbolAddress((void**)&attout, g_attout);

    // 1) qkv = x @ qkv_w + qkv_b : [8192,256]x[256,768]
    {
        dim3 grid(C3 / 64, (BD * PD) / 128);
        sgemm_bias_kernel<<<grid, 256>>>(x, qkv_w, qkv_b, qkv, BD * PD, C3, CD);
    }
    // 2) depthwise 3x3 + bias
    {
        dim3 grid(WD, HD, BD);
        dwconv_kernel<<<grid, 192>>>(qkv, dw_w, dw_b, qkvdw);
    }
    // 3) fold offset/mask weights
    prep_kernel<<<NO, 128>>>(off_pconv_w, off_w, off_b, mask_pconv_w, mask_w, mask_b);
    // 4) offsets + masks for every pixel
    offmask_kernel<<<BD * HD, 256>>>(qkvdw);
    // 5) deformable attention
    {
        dim3 grid(PD / 8, GD, BD);
        attn_kernel<<<grid, 256>>>(qkvdw);
    }
    // 6) out = attout @ proj_w + proj_b : [8192,256]x[256,256]
    {
        dim3 grid(CD / 64, (BD * PD) / 128);
        sgemm_bias_kernel<<<grid, 256>>>(attout, proj_w, proj_b, out, BD * PD, CD, CD);
    }
}

// round 4
// speedup vs baseline: 1.1047x; 1.1028x over previous
#include <cuda_runtime.h>
#include <cstdint>

#define BD 2
#define HD 64
#define WD 64
#define CD 256
#define GD 8
#define KP 9
#define HCD 32
#define PD (HD*WD)       // 4096
#define C3 (3*CD)        // 768
#define NO 160           // 153 outputs padded to 160
#define NF 768           // feature length for offset/mask GEMM

// ---------------- scratch (device globals; no allocation) ----------------
__device__ float g_qkv[BD*PD*C3];      // after qkv linear      (24 MB)
__device__ float g_qkvdw[BD*PD*C3];    // after depthwise conv  (24 MB)
__device__ float g_combW[NF*NO];       // folded offset/mask weights
__device__ float g_combB[NO];          // folded biases (incl. base grid)
__device__ float g_offmask[BD*PD*NO];  // per-pixel 144 offsets + 9 masks
__device__ float g_attout[BD*PD*CD];   // attention output before proj

__constant__ float c_PTS[18] = {-1,-1,-1,0,-1,1,0,-1,0,0,0,1,1,-1,1,0,1,1};

// ---------------- generic SGEMM: C = A[MxK] * B[KxN] + bias --------------
__global__ void __launch_bounds__(256) sgemm_bias_kernel(
    const float* __restrict__ A, const float* __restrict__ B,
    const float* __restrict__ bias, float* __restrict__ C,
    int M, int N, int K)
{
    const int BK = 16;
    __shared__ float As[BK][128];
    __shared__ float Bs[BK][64];
    int tid = threadIdx.x;
    int tx = tid & 15;    // N direction, 4 cols each
    int ty = tid >> 4;    // M direction, 8 rows each
    int row0 = blockIdx.y * 128;
    int col0 = blockIdx.x * 64;

    float acc[8][4];
#pragma unroll
    for (int i = 0; i < 8; i++)
#pragma unroll
        for (int j = 0; j < 4; j++) acc[i][j] = 0.f;

    for (int k0 = 0; k0 < K; k0 += BK) {
#pragma unroll
        for (int i = 0; i < 2; i++) {
            int e = tid + i * 256;
            int m = e >> 2;
            int kk = (e & 3) << 2;
            float4 v = *reinterpret_cast<const float4*>(&A[(size_t)(row0 + m) * K + k0 + kk]);
            As[kk + 0][m] = v.x; As[kk + 1][m] = v.y;
            As[kk + 2][m] = v.z; As[kk + 3][m] = v.w;
        }
        {
            int kk = tid >> 4;
            int n4 = (tid & 15) << 2;
            *reinterpret_cast<float4*>(&Bs[kk][n4]) =
                *reinterpret_cast<const float4*>(&B[(size_t)(k0 + kk) * N + col0 + n4]);
        }
        __syncthreads();
#pragma unroll
        for (int k = 0; k < BK; k++) {
            float a[8], bb[4];
            float4 a0 = *reinterpret_cast<const float4*>(&As[k][ty * 8]);
            float4 a1 = *reinterpret_cast<const float4*>(&As[k][ty * 8 + 4]);
            a[0] = a0.x; a[1] = a0.y; a[2] = a0.z; a[3] = a0.w;
            a[4] = a1.x; a[5] = a1.y; a[6] = a1.z; a[7] = a1.w;
            float4 b0 = *reinterpret_cast<const float4*>(&Bs[k][tx * 4]);
            bb[0] = b0.x; bb[1] = b0.y; bb[2] = b0.z; bb[3] = b0.w;
#pragma unroll
            for (int i = 0; i < 8; i++)
#pragma unroll
                for (int j = 0; j < 4; j++)
                    acc[i][j] += a[i] * bb[j];
        }
        __syncthreads();
    }
    float4 bv = *reinterpret_cast<const float4*>(&bias[col0 + tx * 4]);
#pragma unroll
    for (int i = 0; i < 8; i++) {
        int m = row0 + ty * 8 + i;
        float4 o;
        o.x = acc[i][0] + bv.x; o.y = acc[i][1] + bv.y;
        o.z = acc[i][2] + bv.z; o.w = acc[i][3] + bv.w;
        *reinterpret_cast<float4*>(&C[(size_t)m * N + col0 + tx * 4]) = o;
    }
}

// ---------------- depthwise 3x3 conv, NHWC, 4 px per thread --------------
__global__ void __launch_bounds__(192) dwconv_kernel(
    const float* __restrict__ in, const float* __restrict__ w,
    const float* __restrict__ bias, float* __restrict__ out)
{
    int c = threadIdx.x * 4;
    int x0 = blockIdx.x * 4, y = blockIdx.y, b = blockIdx.z;
    float4 bz = *reinterpret_cast<const float4*>(&bias[c]);
    float4 acc[4] = {bz, bz, bz, bz};
#pragma unroll
    for (int ky = 0; ky < 3; ky++) {
        int yy = y + ky - 1;
        if (yy < 0 || yy >= HD) continue;
        const float* rowp = in + ((size_t)(b * HD + yy) * WD) * C3 + c;
        float4 iv[6];
#pragma unroll
        for (int j = 0; j < 6; j++) {
            int xx = x0 - 1 + j;
            if (xx >= 0 && xx < WD)
                iv[j] = *reinterpret_cast<const float4*>(rowp + (size_t)xx * C3);
            else iv[j] = make_float4(0.f, 0.f, 0.f, 0.f);
        }
#pragma unroll
        for (int kx = 0; kx < 3; kx++) {
            float4 wv = *reinterpret_cast<const float4*>(&w[(ky * 3 + kx) * C3 + c]);
#pragma unroll
            for (int p = 0; p < 4; p++) {
                acc[p].x += wv.x * iv[p + kx].x; acc[p].y += wv.y * iv[p + kx].y;
                acc[p].z += wv.z * iv[p + kx].z; acc[p].w += wv.w * iv[p + kx].w;
            }
        }
    }
#pragma unroll
    for (int p = 0; p < 4; p++)
        *reinterpret_cast<float4*>(
            &out[(size_t)((b * HD + y) * WD + x0 + p) * C3 + c]) = acc[p];
}

// ---------------- fold pconv+proj weights into combW/combB ----------------
__global__ void prep_kernel(
    const float* __restrict__ off_pconv_w, const float* __restrict__ off_w,
    const float* __restrict__ off_b, const float* __restrict__ mask_pconv_w,
    const float* __restrict__ mask_w, const float* __restrict__ mask_b)
{
    int o = blockIdx.x;        // 0..159
    int tid = threadIdx.x;     // 128
    if (o >= 153) {
        for (int f = tid; f < NF; f += 128) g_combW[f * NO + o] = 0.f;
        if (tid == 0) g_combB[o] = 0.f;
        return;
    }
    bool is_mask = (o >= 144);
    int g = 0, j = 0, kk = 0;
    if (!is_mask) { g = o / 18; j = o % 18; } else { kk = o - 144; }

    for (int f = tid; f < NF; f += 128) {
        float s;
        if (f < 576) {
            int t = f >> 6;
            int ic = f & 63;
            s = 0.f;
            if (!is_mask) {
                const float* ow = off_w + (g * 18 + j) * 256;
                const float* pc = off_pconv_w + ((size_t)(g * 64) * 64 + ic) * 9 + t;
                for (int oc = 0; oc < 64; oc++)
                    s += ow[oc] * pc[(size_t)oc * 64 * 9];
            } else {
                const float* mw = mask_w + kk * 256;
                const float* pc = mask_pconv_w + (size_t)ic * 9 + t;
                for (int oc = 0; oc < 64; oc++)
                    s += mw[oc] * pc[(size_t)oc * 64 * 9];
            }
        } else {
            int ch = f - 512;   // 64..255
            s = is_mask ? mask_w[kk * 256 + ch] : off_w[(g * 18 + j) * 256 + ch];
        }
        g_combW[f * NO + o] = s;
    }
    if (tid == 0) {
        g_combB[o] = is_mask ? mask_b[kk]
                             : (off_b[g * 18 + j] + c_PTS[j] * (float)(2 * g + 1));
    }
}

// ---------------- offset/mask GEMM: per image row, 64px x 160 x 768 -------
// Each 32-feature K-chunk lies inside ONE conv tap (or the center block), so
// the gathered values are CONTIGUOUS channels at a fixed (dy,dx): the A-tile
// fill is one coalesced float4 load per thread (NOTE the +c4 channel offset).
__global__ void __launch_bounds__(256) offmask_kernel(const float* __restrict__ qkvdw)
{
    int bh = blockIdx.x;            // 0..127
    int b = bh / HD, h = bh % HD;
    __shared__ float As[32][68];    // [k][px]
    __shared__ float Bs[32][NO];    // [k][o]
    int tid = threadIdx.x;
    int tx = tid & 31;              // 5 output cols
    int ty = tid >> 5;              // 8 pixel rows

    float acc[8][5];
#pragma unroll
    for (int i = 0; i < 8; i++)
#pragma unroll
        for (int j = 0; j < 5; j++) acc[i][j] = 0.f;

    for (int kc = 0; kc < NF; kc += 32) {
        // chunk -> (dy, dx, channel offset)
        int dy, dx, cofs;
        if (kc < 576) {
            int t = kc >> 6;            // tap 0..8 (chunk within one tap)
            dy = t / 3 - 1; dx = t % 3 - 1;
            cofs = kc & 63;             // q channels 0..63
        } else {
            dy = 0; dx = 0;
            cofs = 64 + (kc - 576);     // center channels 64..255
        }
        int yy = h + dy;
        bool rowok = (yy >= 0 && yy < HD);
        const float* rowp = qkvdw + ((size_t)(b * HD + yy) * WD) * C3 + cofs;
#pragma unroll
        for (int i = 0; i < 2; i++) {
            int e = tid + i * 256;      // 0..511
            int px = e >> 3;            // 0..63
            int c4 = (e & 7) << 2;      // 0..28
            int xx = px + dx;
            float4 v = make_float4(0.f, 0.f, 0.f, 0.f);
            if (rowok && xx >= 0 && xx < WD)
                v = *reinterpret_cast<const float4*>(rowp + (size_t)xx * C3 + c4);
            As[c4 + 0][px] = v.x; As[c4 + 1][px] = v.y;
            As[c4 + 2][px] = v.z; As[c4 + 3][px] = v.w;
        }
        // B chunk: 32 x 160 = 1280 float4 slots, 5 per thread
#pragma unroll
        for (int i = 0; i < 5; i++) {
            int e = tid + i * 256;
            int kkk = e / 40;
            int n4 = (e % 40) * 4;
            *reinterpret_cast<float4*>(&Bs[kkk][n4]) =
                *reinterpret_cast<const float4*>(&g_combW[(size_t)(kc + kkk) * NO + n4]);
        }
        __syncthreads();
#pragma unroll
        for (int k = 0; k < 32; k++) {
            float a[8];
            float4 a0 = *reinterpret_cast<const float4*>(&As[k][ty * 8]);
            float4 a1 = *reinterpret_cast<const float4*>(&As[k][ty * 8 + 4]);
            a[0] = a0.x; a[1] = a0.y; a[2] = a0.z; a[3] = a0.w;
            a[4] = a1.x; a[5] = a1.y; a[6] = a1.z; a[7] = a1.w;
            float bb[5];
#pragma unroll
            for (int j = 0; j < 5; j++) bb[j] = Bs[k][tx * 5 + j];
#pragma unroll
            for (int i = 0; i < 8; i++)
#pragma unroll
                for (int j = 0; j < 5; j++)
                    acc[i][j] += a[i] * bb[j];
        }
        __syncthreads();
    }
#pragma unroll
    for (int i = 0; i < 8; i++) {
        int px = ty * 8 + i;
        size_t base = ((size_t)(b * HD + h) * WD + px) * NO;
#pragma unroll
        for (int j = 0; j < 5; j++) {
            int o = tx * 5 + j;
            g_offmask[base + o] = acc[i][j] + g_combB[o];
        }
    }
}

// ---------------- deformable attention: warp per (b,g,pixel) --------------
__global__ void __launch_bounds__(256) attn_kernel(const float* __restrict__ qkvdw)
{
    int warp = threadIdx.x >> 5;
    int lane = threadIdx.x & 31;
    int px = blockIdx.x * 8 + warp;     // 0..4095
    int g = blockIdx.y;
    int b = blockIdx.z;
    int h = px >> 6, w = px & 63;

    const float* om = g_offmask + ((size_t)(b * HD + h) * WD + w) * NO;
    size_t pixbase = (size_t)((b * HD + h) * WD + w) * C3;
    float qv = qkvdw[pixbase + g * HCD + lane] * 0.17677669529663687f; // 32^-0.5

    float attn[KP], vk[KP];
#pragma unroll
    for (int k = 0; k < KP; k++) {
        float ox = om[g * 18 + 2 * k];
        float oy = om[g * 18 + 2 * k + 1];
        float mk = om[144 + k];
        float cx = fminf(fmaxf((float)w + ox, 0.f), (float)(WD - 1));
        float cy = fminf(fmaxf((float)h + oy, 0.f), (float)(HD - 1));
        float x0f = floorf(cx), y0f = floorf(cy);
        float fx = cx - x0f, fy = cy - y0f;
        int x0 = (int)x0f, y0 = (int)y0f;
        int x1 = min(x0 + 1, WD - 1), y1 = min(y0 + 1, HD - 1);
        size_t i00 = (size_t)((b * HD + y0) * WD + x0) * C3 + CD + g * HCD + lane;
        size_t i01 = (size_t)((b * HD + y0) * WD + x1) * C3 + CD + g * HCD + lane;
        size_t i10 = (size_t)((b * HD + y1) * WD + x0) * C3 + CD + g * HCD + lane;
        size_t i11 = (size_t)((b * HD + y1) * WD + x1) * C3 + CD + g * HCD + lane;
        float w00 = (1.f - fx) * (1.f - fy), w01 = fx * (1.f - fy);
        float w10 = (1.f - fx) * fy,         w11 = fx * fy;
        float kvv = qkvdw[i00] * w00 + qkvdw[i01] * w01
                  + qkvdw[i10] * w10 + qkvdw[i11] * w11;
        float vvv = qkvdw[i00 + CD] * w00 + qkvdw[i01 + CD] * w01
                  + qkvdw[i10 + CD] * w10 + qkvdw[i11 + CD] * w11;
        kvv *= mk; vvv *= mk;
        float d = qv * kvv;
#pragma unroll
        for (int s = 16; s; s >>= 1) d += __shfl_xor_sync(0xffffffffu, d, s);
        attn[k] = d;
        vk[k] = vvv;
    }
    float m = attn[0];
#pragma unroll
    for (int k = 1; k < KP; k++) m = fmaxf(m, attn[k]);
    float ssum = 0.f, o = 0.f;
#pragma unroll
    for (int k = 0; k < KP; k++) {
        float e = __expf(attn[k] - m);
        ssum += e;
        o += e * vk[k];
    }
    o /= ssum;
    g_attout[((size_t)((b * HD + h) * WD + w)) * CD + g * HCD + lane] = o;
}

// --------------------------------- launch ---------------------------------
extern "C" void kernel_launch(void* const* d_in, const int* in_sizes, int n_in,
                              void* d_out, int out_size)
{
    const float* x            = (const float*)d_in[0];
    const float* qkv_w        = (const float*)d_in[1];
    const float* qkv_b        = (const float*)d_in[2];
    const float* dw_w         = (const float*)d_in[3];
    const float* dw_b         = (const float*)d_in[4];
    const float* off_pconv_w  = (const float*)d_in[5];
    const float* off_w        = (const float*)d_in[6];
    const float* off_b        = (const float*)d_in[7];
    const float* mask_pconv_w = (const float*)d_in[8];
    const float* mask_w       = (const float*)d_in[9];
    const float* mask_b       = (const float*)d_in[10];
    const float* proj_w       = (const float*)d_in[11];
    const float* proj_b       = (const float*)d_in[12];
    float* out = (float*)d_out;

    float *qkv, *qkvdw, *attout;
    cudaGetSymbolAddress((void**)&qkv, g_qkv);
    cudaGetSymbolAddress((void**)&qkvdw, g_qkvdw);
    cudaGetSymbolAddress((void**)&attout, g_attout);

    // 1) qkv = x @ qkv_w + qkv_b : [8192,256]x[256,768]
    {
        dim3 grid(C3 / 64, (BD * PD) / 128);
        sgemm_bias_kernel<<<grid, 256>>>(x, qkv_w, qkv_b, qkv, BD * PD, C3, CD);
    }
    // 2) depthwise 3x3 + bias (4 px / thread)
    {
        dim3 grid(WD / 4, HD, BD);
        dwconv_kernel<<<grid, 192>>>(qkv, dw_w, dw_b, qkvdw);
    }
    // 3) fold offset/mask weights
    prep_kernel<<<NO, 128>>>(off_pconv_w, off_w, off_b, mask_pconv_w, mask_w, mask_b);
    // 4) offsets + masks for every pixel
    offmask_kernel<<<BD * HD, 256>>>(qkvdw);
    // 5) deformable attention
    {
        dim3 grid(PD / 8, GD, BD);
        attn_kernel<<<grid, 256>>>(qkvdw);
    }
    // 6) out = attout @ proj_w + proj_b : [8192,256]x[256,256]
    {
        dim3 grid(CD / 64, (BD * PD) / 128);
        sgemm_bias_kernel<<<grid, 256>>>(attout, proj_w, proj_b, out, BD * PD, CD, CD);
    }
}

// round 6
// speedup vs baseline: 1.5249x; 1.3803x over previous
#include <cuda_runtime.h>
#include <cuda_fp16.h>
#include <cstdint>

#define BD 2
#define HD 64
#define WD 64
#define CD 256
#define GD 8
#define KP 9
#define HCD 32
#define PD (HD*WD)
#define C3 (3*CD)        // 768
#define NOP 192          // padded offset/mask outputs (153 real)
#define NF 768
#define MR (BD*PD)       // 8192

// ---------------- scratch (device globals; no allocation) ----------------
__device__ float g_qkv[MR*C3];
__device__ float g_qkvdw[MR*C3];
__device__ float g_offmask[MR*NOP];
__device__ float g_combB[NOP];
__device__ __half g_xhi[MR*CD], g_xlo[MR*CD];
__device__ __half g_qwh[C3*CD], g_qwl[C3*CD];      // qkv_w^T hi/lo
__device__ __half g_pwh[CD*CD], g_pwl[CD*CD];      // proj_w^T hi/lo
__device__ __half g_cwh[NOP*NF], g_cwl[NOP*NF];    // combW^T hi/lo
__device__ __half g_fh[MR*NF], g_fl[MR*NF];        // im2col features
__device__ __half g_aoh[MR*CD], g_aol[MR*CD];      // attention out

__constant__ float c_PTS[18] = {-1,-1,-1,0,-1,1,0,-1,0,0,0,1,1,-1,1,0,1,1};

// ---------------- helpers ----------------
__device__ __forceinline__ uint32_t smem_u32(const void* p) {
    uint32_t a;
    asm("{ .reg .u64 t; cvta.to.shared.u64 t, %1; cvt.u32.u64 %0, t; }" : "=r"(a) : "l"(p));
    return a;
}
__device__ __forceinline__ void cp16(uint32_t dst, const void* src) {
    asm volatile("cp.async.cg.shared.global [%0], [%1], 16;" :: "r"(dst), "l"(src));
}
#define CP_COMMIT() asm volatile("cp.async.commit_group;" ::: "memory")
#define CP_WAIT0()  asm volatile("cp.async.wait_group 0;" ::: "memory")
#define LDSM_X4(r, a) asm volatile( \
    "ldmatrix.sync.aligned.m8n8.x4.shared.b16 {%0,%1,%2,%3}, [%4];" \
    : "=r"((r)[0]),"=r"((r)[1]),"=r"((r)[2]),"=r"((r)[3]) : "r"(a))
#define LDSM_X2(r, a) asm volatile( \
    "ldmatrix.sync.aligned.m8n8.x2.shared.b16 {%0,%1}, [%2];" \
    : "=r"((r)[0]),"=r"((r)[1]) : "r"(a))
#define MMA16816(c, a, b) asm volatile( \
    "mma.sync.aligned.m16n8k16.row.col.f32.f16.f16.f32 " \
    "{%0,%1,%2,%3}, {%4,%5,%6,%7}, {%8,%9}, {%0,%1,%2,%3};" \
    : "+f"((c)[0]),"+f"((c)[1]),"+f"((c)[2]),"+f"((c)[3]) \
    : "r"((a)[0]),"r"((a)[1]),"r"((a)[2]),"r"((a)[3]), "r"((b)[0]),"r"((b)[1]))

__device__ __forceinline__ void split1(float v, __half& hi, __half& lo) {
    hi = __float2half_rn(v);
    lo = __float2half_rn(v - __half2float(hi));
}

// ============ split-fp16 tensor-core GEMM: C[M,N] = A·B^T + bias ============
// A[M,K], BT[N,K] hi/lo halves. Tile 128x64, BK=32, 256 thr (8 warps 4x2).
__global__ void __launch_bounds__(256, 2) gemm_kernel(
    const __half* __restrict__ Ah, const __half* __restrict__ Al,
    const __half* __restrict__ Bh, const __half* __restrict__ Bl,
    const float* __restrict__ bias, float* __restrict__ C, int N, int K)
{
    __shared__ __half sAh[128][40], sAl[128][40], sBh[64][40], sBl[64][40];
    int tid = threadIdx.x;
    int warp = tid >> 5, lane = tid & 31;
    int wm = warp >> 1, wn = warp & 1;     // 4 x 2 warp grid
    int row0 = blockIdx.y * 128, col0 = blockIdx.x * 64;

    float acc[2][4][4];
#pragma unroll
    for (int mi = 0; mi < 2; mi++)
#pragma unroll
        for (int j = 0; j < 4; j++)
#pragma unroll
            for (int r = 0; r < 4; r++) acc[mi][j][r] = 0.f;

    for (int k0 = 0; k0 < K; k0 += 32) {
        // stage A: 128 rows x 32 halves (hi & lo), 16B per cp
#pragma unroll
        for (int i = 0; i < 2; i++) {
            int e = tid + i * 256;              // 0..511
            int r = e >> 2, cs = (e & 3) * 8;
            size_t ga = (size_t)(row0 + r) * K + k0 + cs;
            cp16(smem_u32(&sAh[r][cs]), Ah + ga);
            cp16(smem_u32(&sAl[r][cs]), Al + ga);
        }
        // stage B: 64 rows x 32 halves
        {
            int r = tid >> 2, cs = (tid & 3) * 8;
            size_t gb = (size_t)(col0 + r) * K + k0 + cs;
            cp16(smem_u32(&sBh[r][cs]), Bh + gb);
            cp16(smem_u32(&sBl[r][cs]), Bl + gb);
        }
        CP_COMMIT();
        CP_WAIT0();
        __syncthreads();

#pragma unroll
        for (int ks = 0; ks < 2; ks++) {
            uint32_t aH[2][4], aL[2][4], bH[4][2], bL[4][2];
#pragma unroll
            for (int mi = 0; mi < 2; mi++) {
                int rowa = wm * 32 + mi * 16 + (lane & 15);
                int cola = ks * 16 + (lane >> 4) * 8;
                LDSM_X4(aH[mi], smem_u32(&sAh[rowa][cola]));
                LDSM_X4(aL[mi], smem_u32(&sAl[rowa][cola]));
            }
#pragma unroll
            for (int j = 0; j < 4; j++) {
                int l16 = lane & 15;
                int rowb = wn * 32 + j * 8 + (l16 & 7);
                int colb = ks * 16 + ((l16 >> 3) & 1) * 8;
                LDSM_X2(bH[j], smem_u32(&sBh[rowb][colb]));
                LDSM_X2(bL[j], smem_u32(&sBl[rowb][colb]));
            }
#pragma unroll
            for (int mi = 0; mi < 2; mi++)
#pragma unroll
                for (int j = 0; j < 4; j++) {
                    MMA16816(acc[mi][j], aH[mi], bH[j]);
                    MMA16816(acc[mi][j], aH[mi], bL[j]);
                    MMA16816(acc[mi][j], aL[mi], bH[j]);
                }
        }
        __syncthreads();
    }

    // epilogue: direct float2 stores + bias
    int g = lane >> 2, t = lane & 3;
#pragma unroll
    for (int mi = 0; mi < 2; mi++)
#pragma unroll
        for (int j = 0; j < 4; j++) {
            int col = col0 + wn * 32 + j * 8 + t * 2;
            float2 bv = *reinterpret_cast<const float2*>(&bias[col]);
            int r0 = row0 + wm * 32 + mi * 16 + g;
            float2 o0 = make_float2(acc[mi][j][0] + bv.x, acc[mi][j][1] + bv.y);
            float2 o1 = make_float2(acc[mi][j][2] + bv.x, acc[mi][j][3] + bv.y);
            *reinterpret_cast<float2*>(&C[(size_t)r0 * N + col]) = o0;
            *reinterpret_cast<float2*>(&C[(size_t)(r0 + 8) * N + col]) = o1;
        }
}

// ---------------- x -> hi/lo ----------------
__global__ void __launch_bounds__(256) cvt_x_kernel(const float* __restrict__ x) {
    int i = (blockIdx.x * 256 + threadIdx.x) * 4;
    float4 v = *reinterpret_cast<const float4*>(&x[i]);
    float f[4] = {v.x, v.y, v.z, v.w};
#pragma unroll
    for (int j = 0; j < 4; j++) {
        __half h, l; split1(f[j], h, l);
        g_xhi[i + j] = h; g_xlo[i + j] = l;
    }
}

// ---------------- W[K][N] -> T[N][K] hi/lo ----------------
__global__ void wsplitT_kernel(const float* __restrict__ W,
                               __half* __restrict__ Th,
                               __half* __restrict__ Tl, int Kk, int Nn) {
    int o = blockIdx.x;
    for (int k = threadIdx.x; k < Kk; k += blockDim.x) {
        __half h, l; split1(W[(size_t)k * Nn + o], h, l);
        Th[(size_t)o * Kk + k] = h;
        Tl[(size_t)o * Kk + k] = l;
    }
}

// ---------------- depthwise 3x3, 4 px/thread ----------------
__global__ void __launch_bounds__(192) dwconv_kernel(
    const float* __restrict__ in, const float* __restrict__ w,
    const float* __restrict__ bias, float* __restrict__ out)
{
    int c = threadIdx.x * 4;
    int x0 = blockIdx.x * 4, y = blockIdx.y, b = blockIdx.z;
    float4 bz = *reinterpret_cast<const float4*>(&bias[c]);
    float4 acc[4] = {bz, bz, bz, bz};
#pragma unroll
    for (int ky = 0; ky < 3; ky++) {
        int yy = y + ky - 1;
        if (yy < 0 || yy >= HD) continue;
        const float* rowp = in + ((size_t)(b * HD + yy) * WD) * C3 + c;
        float4 iv[6];
#pragma unroll
        for (int j = 0; j < 6; j++) {
            int xx = x0 - 1 + j;
            iv[j] = (xx >= 0 && xx < WD)
                ? *reinterpret_cast<const float4*>(rowp + (size_t)xx * C3)
                : make_float4(0.f, 0.f, 0.f, 0.f);
        }
#pragma unroll
        for (int kx = 0; kx < 3; kx++) {
            float4 wv = *reinterpret_cast<const float4*>(&w[(ky * 3 + kx) * C3 + c]);
#pragma unroll
            for (int p = 0; p < 4; p++) {
                acc[p].x += wv.x * iv[p + kx].x; acc[p].y += wv.y * iv[p + kx].y;
                acc[p].z += wv.z * iv[p + kx].z; acc[p].w += wv.w * iv[p + kx].w;
            }
        }
    }
#pragma unroll
    for (int p = 0; p < 4; p++)
        *reinterpret_cast<float4*>(&out[(size_t)((b * HD + y) * WD + x0 + p) * C3 + c]) = acc[p];
}

// ---------------- fold pconv+proj -> combW^T hi/lo + bias ----------------
__global__ void prep_kernel(
    const float* __restrict__ off_pconv_w, const float* __restrict__ off_w,
    const float* __restrict__ off_b, const float* __restrict__ mask_pconv_w,
    const float* __restrict__ mask_w, const float* __restrict__ mask_b)
{
    int o = blockIdx.x;        // 0..191
    int tid = threadIdx.x;     // 128
    if (o >= 153) {
        for (int f = tid; f < NF; f += 128) {
            g_cwh[(size_t)o * NF + f] = __float2half_rn(0.f);
            g_cwl[(size_t)o * NF + f] = __float2half_rn(0.f);
        }
        if (tid == 0) g_combB[o] = 0.f;
        return;
    }
    bool is_mask = (o >= 144);
    int g = 0, j = 0, kk = 0;
    if (!is_mask) { g = o / 18; j = o % 18; } else { kk = o - 144; }

    for (int f = tid; f < NF; f += 128) {
        float s;
        if (f < 576) {
            int t = f >> 6, ic = f & 63;
            s = 0.f;
            if (!is_mask) {
                const float* ow = off_w + (g * 18 + j) * 256;
                const float* pc = off_pconv_w + ((size_t)(g * 64) * 64 + ic) * 9 + t;
                for (int oc = 0; oc < 64; oc++) s += ow[oc] * pc[(size_t)oc * 64 * 9];
            } else {
                const float* mw = mask_w + kk * 256;
                const float* pc = mask_pconv_w + (size_t)ic * 9 + t;
                for (int oc = 0; oc < 64; oc++) s += mw[oc] * pc[(size_t)oc * 64 * 9];
            }
        } else {
            int ch = f - 512;
            s = is_mask ? mask_w[kk * 256 + ch] : off_w[(g * 18 + j) * 256 + ch];
        }
        __half h, l; split1(s, h, l);
        g_cwh[(size_t)o * NF + f] = h;
        g_cwl[(size_t)o * NF + f] = l;
    }
    if (tid == 0)
        g_combB[o] = is_mask ? mask_b[kk]
                             : (off_b[g * 18 + j] + c_PTS[j] * (float)(2 * g + 1));
}

// ---------------- im2col feature matrix [8192][768], hi/lo fp16 ----------
__global__ void __launch_bounds__(256) im2col_kernel(const float* __restrict__ qkvdw)
{
    int bh = blockIdx.x;                   // 0..127
    int b = bh >> 6, h = bh & 63;
    int tid = threadIdx.x;
#pragma unroll
    for (int t = 0; t < 9; t++) {
        int yy = h + t / 3 - 1;
        int dx = t % 3 - 1;
        bool rowok = (yy >= 0 && yy < HD);
        const float* rowp = qkvdw + (size_t)(b * HD + yy) * WD * C3;
#pragma unroll
        for (int it = 0; it < 4; it++) {
            int e = tid + it * 256;        // 0..1023
            int px = e >> 4, c4 = (e & 15) << 2;
            int xx = px + dx;
            float4 v = make_float4(0.f, 0.f, 0.f, 0.f);
            if (rowok && xx >= 0 && xx < WD)
                v = *reinterpret_cast<const float4*>(rowp + (size_t)xx * C3 + c4);
            size_t oo = (size_t)(bh * 64 + px) * NF + t * 64 + c4;
            __half h0,h1,h2,h3,l0,l1,l2,l3;
            split1(v.x,h0,l0); split1(v.y,h1,l1); split1(v.z,h2,l2); split1(v.w,h3,l3);
            *reinterpret_cast<__half2*>(&g_fh[oo])   = __halves2half2(h0,h1);
            *reinterpret_cast<__half2*>(&g_fh[oo+2]) = __halves2half2(h2,h3);
            *reinterpret_cast<__half2*>(&g_fl[oo])   = __halves2half2(l0,l1);
            *reinterpret_cast<__half2*>(&g_fl[oo+2]) = __halves2half2(l2,l3);
        }
    }
    const float* crow = qkvdw + (size_t)(b * HD + h) * WD * C3;
#pragma unroll
    for (int it = 0; it < 12; it++) {
        int e = tid + it * 256;            // 0..3071
        int px = e / 48, c4 = (e % 48) << 2;
        float4 v = *reinterpret_cast<const float4*>(crow + (size_t)px * C3 + 64 + c4);
        size_t oo = (size_t)(bh * 64 + px) * NF + 576 + c4;
        __half h0,h1,h2,h3,l0,l1,l2,l3;
        split1(v.x,h0,l0); split1(v.y,h1,l1); split1(v.z,h2,l2); split1(v.w,h3,l3);
        *reinterpret_cast<__half2*>(&g_fh[oo])   = __halves2half2(h0,h1);
        *reinterpret_cast<__half2*>(&g_fh[oo+2]) = __halves2half2(h2,h3);
        *reinterpret_cast<__half2*>(&g_fl[oo])   = __halves2half2(l0,l1);
        *reinterpret_cast<__half2*>(&g_fl[oo+2]) = __halves2half2(l2,l3);
    }
}

// ---------------- deformable attention: warp per (b,g,pixel) --------------
__global__ void __launch_bounds__(256) attn_kernel(const float* __restrict__ qkvdw)
{
    int warp = threadIdx.x >> 5, lane = threadIdx.x & 31;
    int px = blockIdx.x * 8 + warp;
    int g = blockIdx.y, b = blockIdx.z;
    int h = px >> 6, w = px & 63;

    const float* om = g_offmask + ((size_t)(b * HD + h) * WD + w) * NOP;
    size_t pixbase = (size_t)((b * HD + h) * WD + w) * C3;
    float qv = qkvdw[pixbase + g * HCD + lane] * 0.17677669529663687f;

    float attn[KP], vk[KP];
#pragma unroll
    for (int k = 0; k < KP; k++) {
        float ox = om[g * 18 + 2 * k], oy = om[g * 18 + 2 * k + 1], mk = om[144 + k];
        float cx = fminf(fmaxf((float)w + ox, 0.f), (float)(WD - 1));
        float cy = fminf(fmaxf((float)h + oy, 0.f), (float)(HD - 1));
        float x0f = floorf(cx), y0f = floorf(cy);
        float fx = cx - x0f, fy = cy - y0f;
        int x0 = (int)x0f, y0 = (int)y0f;
        int x1 = min(x0 + 1, WD - 1), y1 = min(y0 + 1, HD - 1);
        size_t i00 = (size_t)((b * HD + y0) * WD + x0) * C3 + CD + g * HCD + lane;
        size_t i01 = (size_t)((b * HD + y0) * WD + x1) * C3 + CD + g * HCD + lane;
        size_t i10 = (size_t)((b * HD + y1) * WD + x0) * C3 + CD + g * HCD + lane;
        size_t i11 = (size_t)((b * HD + y1) * WD + x1) * C3 + CD + g * HCD + lane;
        float w00 = (1.f - fx) * (1.f - fy), w01 = fx * (1.f - fy);
        float w10 = (1.f - fx) * fy,         w11 = fx * fy;
        float kvv = qkvdw[i00]*w00 + qkvdw[i01]*w01 + qkvdw[i10]*w10 + qkvdw[i11]*w11;
        float vvv = qkvdw[i00+CD]*w00 + qkvdw[i01+CD]*w01 + qkvdw[i10+CD]*w10 + qkvdw[i11+CD]*w11;
        kvv *= mk; vvv *= mk;
        float d = qv * kvv;
#pragma unroll
        for (int s = 16; s; s >>= 1) d += __shfl_xor_sync(0xffffffffu, d, s);
        attn[k] = d;
        vk[k] = vvv;
    }
    float m = attn[0];
#pragma unroll
    for (int k = 1; k < KP; k++) m = fmaxf(m, attn[k]);
    float ssum = 0.f, o = 0.f;
#pragma unroll
    for (int k = 0; k < KP; k++) {
        float e = __expf(attn[k] - m);
        ssum += e;
        o += e * vk[k];
    }
    o /= ssum;
    size_t oi = ((size_t)((b * HD + h) * WD + w)) * CD + g * HCD + lane;
    __half hh, ll; split1(o, hh, ll);
    g_aoh[oi] = hh; g_aol[oi] = ll;
}

// --------------------------------- launch ---------------------------------
extern "C" void kernel_launch(void* const* d_in, const int* in_sizes, int n_in,
                              void* d_out, int out_size)
{
    const float* x            = (const float*)d_in[0];
    const float* qkv_w        = (const float*)d_in[1];
    const float* qkv_b        = (const float*)d_in[2];
    const float* dw_w         = (const float*)d_in[3];
    const float* dw_b         = (const float*)d_in[4];
    const float* off_pconv_w  = (const float*)d_in[5];
    const float* off_w        = (const float*)d_in[6];
    const float* off_b        = (const float*)d_in[7];
    const float* mask_pconv_w = (const float*)d_in[8];
    const float* mask_w       = (const float*)d_in[9];
    const float* mask_b       = (const float*)d_in[10];
    const float* proj_w       = (const float*)d_in[11];
    const float* proj_b       = (const float*)d_in[12];
    float* out = (float*)d_out;

    __half *xh, *xl, *qwh, *qwl, *pwh, *pwl, *cwh, *cwl, *fh, *fl, *aoh, *aol;
    float *qkv, *qkvdw, *combB, *offmask;
    cudaGetSymbolAddress((void**)&xh, g_xhi);   cudaGetSymbolAddress((void**)&xl, g_xlo);
    cudaGetSymbolAddress((void**)&qwh, g_qwh);  cudaGetSymbolAddress((void**)&qwl, g_qwl);
    cudaGetSymbolAddress((void**)&pwh, g_pwh);  cudaGetSymbolAddress((void**)&pwl, g_pwl);
    cudaGetSymbolAddress((void**)&cwh, g_cwh);  cudaGetSymbolAddress((void**)&cwl, g_cwl);
    cudaGetSymbolAddress((void**)&fh, g_fh);    cudaGetSymbolAddress((void**)&fl, g_fl);
    cudaGetSymbolAddress((void**)&aoh, g_aoh);  cudaGetSymbolAddress((void**)&aol, g_aol);
    cudaGetSymbolAddress((void**)&qkv, g_qkv);
    cudaGetSymbolAddress((void**)&qkvdw, g_qkvdw);
    cudaGetSymbolAddress((void**)&combB, g_combB);
    cudaGetSymbolAddress((void**)&offmask, g_offmask);

    // conversions / weight prep
    cvt_x_kernel<<<(MR * CD) / 1024, 256>>>(x);
    wsplitT_kernel<<<C3, 256>>>(qkv_w, qwh, qwl, CD, C3);
    wsplitT_kernel<<<CD, 256>>>(proj_w, pwh, pwl, CD, CD);
    prep_kernel<<<NOP, 128>>>(off_pconv_w, off_w, off_b, mask_pconv_w, mask_w, mask_b);

    // 1) qkv GEMM: [8192,256] -> [8192,768]
    {
        dim3 grid(C3 / 64, MR / 128);
        gemm_kernel<<<grid, 256>>>(xh, xl, qwh, qwl, qkv_b, qkv, C3, CD);
    }
    // 2) depthwise conv
    {
        dim3 grid(WD / 4, HD, BD);
        dwconv_kernel<<<grid, 192>>>(qkv, dw_w, dw_b, qkvdw);
    }
    // 3) im2col features
    im2col_kernel<<<BD * HD, 256>>>(qkvdw);
    // 4) offset/mask GEMM: [8192,768] -> [8192,192]
    {
        dim3 grid(NOP / 64, MR / 128);
        gemm_kernel<<<grid, 256>>>(fh, fl, cwh, cwl, combB, offmask, NOP, NF);
    }
    // 5) attention
    {
        dim3 grid(PD / 8, GD, BD);
        attn_kernel<<<grid, 256>>>(qkvdw);
    }
    // 6) proj GEMM: [8192,256] -> [8192,256]
    {
        dim3 grid(CD / 64, MR / 128);
        gemm_kernel<<<grid, 256>>>(aoh, aol, pwh, pwl, proj_b, out, CD, CD);
    }
}

// round 7
// speedup vs baseline: 1.5389x; 1.0092x over previous
#include <cuda_runtime.h>
#include <cuda_fp16.h>
#include <cstdint>

#define BD 2
#define HD 64
#define WD 64
#define CD 256
#define GD 8
#define KP 9
#define HCD 32
#define PD (HD*WD)
#define C3 (3*CD)        // 768
#define NOP 192          // padded offset/mask outputs (153 real)
#define NF 768
#define MR (BD*PD)       // 8192

// ---------------- scratch (device globals; no allocation) ----------------
__device__ float  g_qkv[MR*C3];          // after qkv GEMM
__device__ float  g_q[MR*CD];            // q after dwconv (fp32)
__device__ float2 g_kv[MR*CD];           // {k,v} interleaved after dwconv
__device__ float  g_offmask[MR*NOP];
__device__ float  g_combB[NOP];
__device__ __half g_xhi[MR*CD], g_xlo[MR*CD];
__device__ __half g_qwh[C3*CD], g_qwl[C3*CD];      // qkv_w^T hi/lo
__device__ __half g_pwh[CD*CD], g_pwl[CD*CD];      // proj_w^T hi/lo
__device__ __half g_cwh[NOP*NF], g_cwl[NOP*NF];    // combW^T hi/lo
__device__ __half g_fh[MR*NF], g_fl[MR*NF];        // im2col features
__device__ __half g_aoh[MR*CD], g_aol[MR*CD];      // attention out

__constant__ float c_PTS[18] = {-1,-1,-1,0,-1,1,0,-1,0,0,0,1,1,-1,1,0,1,1};

// ---------------- helpers ----------------
__device__ __forceinline__ uint32_t smem_u32(const void* p) {
    uint32_t a;
    asm("{ .reg .u64 t; cvta.to.shared.u64 t, %1; cvt.u32.u64 %0, t; }" : "=r"(a) : "l"(p));
    return a;
}
__device__ __forceinline__ void cp16(uint32_t dst, const void* src) {
    asm volatile("cp.async.cg.shared.global [%0], [%1], 16;" :: "r"(dst), "l"(src));
}
#define CP_COMMIT() asm volatile("cp.async.commit_group;" ::: "memory")
#define CP_WAIT0()  asm volatile("cp.async.wait_group 0;" ::: "memory")
#define CP_WAIT1()  asm volatile("cp.async.wait_group 1;" ::: "memory")
#define LDSM_X4(r, a) asm volatile( \
    "ldmatrix.sync.aligned.m8n8.x4.shared.b16 {%0,%1,%2,%3}, [%4];" \
    : "=r"((r)[0]),"=r"((r)[1]),"=r"((r)[2]),"=r"((r)[3]) : "r"(a))
#define LDSM_X2(r, a) asm volatile( \
    "ldmatrix.sync.aligned.m8n8.x2.shared.b16 {%0,%1}, [%2];" \
    : "=r"((r)[0]),"=r"((r)[1]) : "r"(a))
#define MMA16816(c, a, b) asm volatile( \
    "mma.sync.aligned.m16n8k16.row.col.f32.f16.f16.f32 " \
    "{%0,%1,%2,%3}, {%4,%5,%6,%7}, {%8,%9}, {%0,%1,%2,%3};" \
    : "+f"((c)[0]),"+f"((c)[1]),"+f"((c)[2]),"+f"((c)[3]) \
    : "r"((a)[0]),"r"((a)[1]),"r"((a)[2]),"r"((a)[3]), "r"((b)[0]),"r"((b)[1]))

__device__ __forceinline__ void split1(float v, __half& hi, __half& lo) {
    hi = __float2half_rn(v);
    lo = __float2half_rn(v - __half2float(hi));
}

// ============ split-fp16 tensor-core GEMM, double-buffered ============
// C[M,N] = A·B^T + bias. A[M,K], BT[N,K] hi/lo. Tile 128x64, BK=32, 256 thr.
#define A_OFF(s,r,c) ((s)*128*40 + (r)*40 + (c))
#define B_OFF(s,r,c) ((s)*64*40 + (r)*40 + (c))
#define GEMM_SMEM (2*(2*128*40 + 2*64*40) * 2)   // 61440 bytes

__global__ void __launch_bounds__(256, 2) gemm_kernel(
    const __half* __restrict__ Ah, const __half* __restrict__ Al,
    const __half* __restrict__ Bh, const __half* __restrict__ Bl,
    const float* __restrict__ bias, float* __restrict__ C, int N, int K)
{
    extern __shared__ __half sm[];
    __half* sAh = sm;                     // [2][128][40]
    __half* sAl = sAh + 2*128*40;
    __half* sBh = sAl + 2*128*40;         // [2][64][40]
    __half* sBl = sBh + 2*64*40;

    int tid = threadIdx.x;
    int warp = tid >> 5, lane = tid & 31;
    int wm = warp >> 1, wn = warp & 1;
    int row0 = blockIdx.y * 128, col0 = blockIdx.x * 64;

    float acc[2][4][4];
#pragma unroll
    for (int mi = 0; mi < 2; mi++)
#pragma unroll
        for (int j = 0; j < 4; j++)
#pragma unroll
            for (int r = 0; r < 4; r++) acc[mi][j][r] = 0.f;

#define STAGE(kc, s) do { \
    int k0 = (kc) << 5; \
    _Pragma("unroll") \
    for (int i = 0; i < 2; i++) { \
        int e = tid + i * 256; \
        int r = e >> 2, cs = (e & 3) * 8; \
        size_t ga = (size_t)(row0 + r) * K + k0 + cs; \
        cp16(smem_u32(&sAh[A_OFF(s, r, cs)]), Ah + ga); \
        cp16(smem_u32(&sAl[A_OFF(s, r, cs)]), Al + ga); \
    } \
    { int r = tid >> 2, cs = (tid & 3) * 8; \
      size_t gb = (size_t)(col0 + r) * K + k0 + cs; \
      cp16(smem_u32(&sBh[B_OFF(s, r, cs)]), Bh + gb); \
      cp16(smem_u32(&sBl[B_OFF(s, r, cs)]), Bl + gb); } \
} while (0)

    int nk = K >> 5;
    STAGE(0, 0);
    CP_COMMIT();
    for (int kc = 0; kc < nk; kc++) {
        int cur = kc & 1;
        if (kc + 1 < nk) { STAGE(kc + 1, cur ^ 1); CP_COMMIT(); CP_WAIT1(); }
        else             { CP_WAIT0(); }
        __syncthreads();

#pragma unroll
        for (int ks = 0; ks < 2; ks++) {
            uint32_t aH[2][4], aL[2][4], bH[4][2], bL[4][2];
#pragma unroll
            for (int mi = 0; mi < 2; mi++) {
                int rowa = wm * 32 + mi * 16 + (lane & 15);
                int cola = ks * 16 + (lane >> 4) * 8;
                LDSM_X4(aH[mi], smem_u32(&sAh[A_OFF(cur, rowa, cola)]));
                LDSM_X4(aL[mi], smem_u32(&sAl[A_OFF(cur, rowa, cola)]));
            }
#pragma unroll
            for (int j = 0; j < 4; j++) {
                int l16 = lane & 15;
                int rowb = wn * 32 + j * 8 + (l16 & 7);
                int colb = ks * 16 + ((l16 >> 3) & 1) * 8;
                LDSM_X2(bH[j], smem_u32(&sBh[B_OFF(cur, rowb, colb)]));
                LDSM_X2(bL[j], smem_u32(&sBl[B_OFF(cur, rowb, colb)]));
            }
#pragma unroll
            for (int mi = 0; mi < 2; mi++)
#pragma unroll
                for (int j = 0; j < 4; j++) {
                    MMA16816(acc[mi][j], aH[mi], bH[j]);
                    MMA16816(acc[mi][j], aH[mi], bL[j]);
                    MMA16816(acc[mi][j], aL[mi], bH[j]);
                }
        }
        __syncthreads();
    }
#undef STAGE

    int g = lane >> 2, t = lane & 3;
#pragma unroll
    for (int mi = 0; mi < 2; mi++)
#pragma unroll
        for (int j = 0; j < 4; j++) {
            int col = col0 + wn * 32 + j * 8 + t * 2;
            float2 bv = *reinterpret_cast<const float2*>(&bias[col]);
            int r0 = row0 + wm * 32 + mi * 16 + g;
            float2 o0 = make_float2(acc[mi][j][0] + bv.x, acc[mi][j][1] + bv.y);
            float2 o1 = make_float2(acc[mi][j][2] + bv.x, acc[mi][j][3] + bv.y);
            *reinterpret_cast<float2*>(&C[(size_t)r0 * N + col]) = o0;
            *reinterpret_cast<float2*>(&C[(size_t)(r0 + 8) * N + col]) = o1;
        }
}

// ------- merged conversions: x split + qkv_w^T split + proj_w^T split -------
__global__ void __launch_bounds__(256) convert_all_kernel(
    const float* __restrict__ x, const float* __restrict__ qkv_w,
    const float* __restrict__ proj_w)
{
    int bid = blockIdx.x, tid = threadIdx.x;
    if (bid < 2048) {                       // x -> hi/lo, 4 elems/thread
        int i = (bid * 256 + tid) * 4;
        float4 v = *reinterpret_cast<const float4*>(&x[i]);
        float f[4] = {v.x, v.y, v.z, v.w};
#pragma unroll
        for (int j = 0; j < 4; j++) {
            __half h, l; split1(f[j], h, l);
            g_xhi[i + j] = h; g_xlo[i + j] = l;
        }
    } else if (bid < 2048 + C3) {           // qkv_w [256][768] -> T hi/lo
        int o = bid - 2048;
        __half h, l; split1(qkv_w[(size_t)tid * C3 + o], h, l);
        g_qwh[(size_t)o * CD + tid] = h;
        g_qwl[(size_t)o * CD + tid] = l;
    } else {                                // proj_w [256][256] -> T hi/lo
        int o = bid - 2048 - C3;
        __half h, l; split1(proj_w[(size_t)tid * CD + o], h, l);
        g_pwh[(size_t)o * CD + tid] = h;
        g_pwl[(size_t)o * CD + tid] = l;
    }
}

// ---------------- depthwise 3x3, 4 px/thread, split q / kv outputs --------
__global__ void __launch_bounds__(192) dwconv_kernel(
    const float* __restrict__ in, const float* __restrict__ w,
    const float* __restrict__ bias)
{
    int c = threadIdx.x * 4;
    int x0 = blockIdx.x * 4, y = blockIdx.y, b = blockIdx.z;
    float4 bz = *reinterpret_cast<const float4*>(&bias[c]);
    float4 acc[4] = {bz, bz, bz, bz};
#pragma unroll
    for (int ky = 0; ky < 3; ky++) {
        int yy = y + ky - 1;
        if (yy < 0 || yy >= HD) continue;
        const float* rowp = in + ((size_t)(b * HD + yy) * WD) * C3 + c;
        float4 iv[6];
#pragma unroll
        for (int j = 0; j < 6; j++) {
            int xx = x0 - 1 + j;
            iv[j] = (xx >= 0 && xx < WD)
                ? *reinterpret_cast<const float4*>(rowp + (size_t)xx * C3)
                : make_float4(0.f, 0.f, 0.f, 0.f);
        }
#pragma unroll
        for (int kx = 0; kx < 3; kx++) {
            float4 wv = *reinterpret_cast<const float4*>(&w[(ky * 3 + kx) * C3 + c]);
#pragma unroll
            for (int p = 0; p < 4; p++) {
                acc[p].x += wv.x * iv[p + kx].x; acc[p].y += wv.y * iv[p + kx].y;
                acc[p].z += wv.z * iv[p + kx].z; acc[p].w += wv.w * iv[p + kx].w;
            }
        }
    }
#pragma unroll
    for (int p = 0; p < 4; p++) {
        size_t pix = (size_t)(b * HD + y) * WD + x0 + p;
        if (c < CD) {
            *reinterpret_cast<float4*>(&g_q[pix * CD + c]) = acc[p];
        } else if (c < 2 * CD) {
            float2* bp = &g_kv[pix * CD + (c - CD)];
            bp[0].x = acc[p].x; bp[1].x = acc[p].y;
            bp[2].x = acc[p].z; bp[3].x = acc[p].w;
        } else {
            float2* bp = &g_kv[pix * CD + (c - 2 * CD)];
            bp[0].y = acc[p].x; bp[1].y = acc[p].y;
            bp[2].y = acc[p].z; bp[3].y = acc[p].w;
        }
    }
}

// ---------------- fold pconv+proj -> combW^T hi/lo + bias ----------------
// grid (NOP, 6): each thread handles exactly one feature f.
__global__ void __launch_bounds__(128) prep_kernel(
    const float* __restrict__ off_pconv_w, const float* __restrict__ off_w,
    const float* __restrict__ off_b, const float* __restrict__ mask_pconv_w,
    const float* __restrict__ mask_w, const float* __restrict__ mask_b)
{
    int o = blockIdx.x;
    int f = blockIdx.y * 128 + threadIdx.x;
    if (o >= 153) {
        g_cwh[(size_t)o * NF + f] = __float2half_rn(0.f);
        g_cwl[(size_t)o * NF + f] = __float2half_rn(0.f);
        if (threadIdx.x == 0 && blockIdx.y == 0) g_combB[o] = 0.f;
        return;
    }
    bool is_mask = (o >= 144);
    int g = 0, j = 0, kk = 0;
    if (!is_mask) { g = o / 18; j = o % 18; } else { kk = o - 144; }

    float s;
    if (f < 576) {
        int t = f >> 6, ic = f & 63;
        s = 0.f;
        if (!is_mask) {
            const float* ow = off_w + (g * 18 + j) * 256;
            const float* pc = off_pconv_w + ((size_t)(g * 64) * 64 + ic) * 9 + t;
#pragma unroll 4
            for (int oc = 0; oc < 64; oc++) s += ow[oc] * pc[(size_t)oc * 64 * 9];
        } else {
            const float* mw = mask_w + kk * 256;
            const float* pc = mask_pconv_w + (size_t)ic * 9 + t;
#pragma unroll 4
            for (int oc = 0; oc < 64; oc++) s += mw[oc] * pc[(size_t)oc * 64 * 9];
        }
    } else {
        int ch = f - 512;
        s = is_mask ? mask_w[kk * 256 + ch] : off_w[(g * 18 + j) * 256 + ch];
    }
    __half h, l; split1(s, h, l);
    g_cwh[(size_t)o * NF + f] = h;
    g_cwl[(size_t)o * NF + f] = l;
    if (threadIdx.x == 0 && blockIdx.y == 0)
        g_combB[o] = is_mask ? mask_b[kk]
                             : (off_b[g * 18 + j] + c_PTS[j] * (float)(2 * g + 1));
}

// ---------------- im2col feature matrix from g_q, hi/lo fp16 -------------
__global__ void __launch_bounds__(256) im2col_kernel()
{
    int bh = blockIdx.x;                   // 0..127
    int b = bh >> 6, h = bh & 63;
    int tid = threadIdx.x;
#pragma unroll
    for (int t = 0; t < 9; t++) {
        int yy = h + t / 3 - 1;
        int dx = t % 3 - 1;
        bool rowok = (yy >= 0 && yy < HD);
        const float* rowp = g_q + (size_t)(b * HD + yy) * WD * CD;
#pragma unroll
        for (int it = 0; it < 4; it++) {
            int e = tid + it * 256;        // 0..1023
            int px = e >> 4, c4 = (e & 15) << 2;
            int xx = px + dx;
            float4 v = make_float4(0.f, 0.f, 0.f, 0.f);
            if (rowok && xx >= 0 && xx < WD)
                v = *reinterpret_cast<const float4*>(rowp + (size_t)xx * CD + c4);
            size_t oo = (size_t)(bh * 64 + px) * NF + t * 64 + c4;
            __half h0,h1,h2,h3,l0,l1,l2,l3;
            split1(v.x,h0,l0); split1(v.y,h1,l1); split1(v.z,h2,l2); split1(v.w,h3,l3);
            *reinterpret_cast<__half2*>(&g_fh[oo])   = __halves2half2(h0,h1);
            *reinterpret_cast<__half2*>(&g_fh[oo+2]) = __halves2half2(h2,h3);
            *reinterpret_cast<__half2*>(&g_fl[oo])   = __halves2half2(l0,l1);
            *reinterpret_cast<__half2*>(&g_fl[oo+2]) = __halves2half2(l2,l3);
        }
    }
    const float* crow = g_q + (size_t)(b * HD + h) * WD * CD;
#pragma unroll
    for (int it = 0; it < 12; it++) {
        int e = tid + it * 256;            // 0..3071
        int px = e / 48, c4 = (e % 48) << 2;
        float4 v = *reinterpret_cast<const float4*>(crow + (size_t)px * CD + 64 + c4);
        size_t oo = (size_t)(bh * 64 + px) * NF + 576 + c4;
        __half h0,h1,h2,h3,l0,l1,l2,l3;
        split1(v.x,h0,l0); split1(v.y,h1,l1); split1(v.z,h2,l2); split1(v.w,h3,l3);
        *reinterpret_cast<__half2*>(&g_fh[oo])   = __halves2half2(h0,h1);
        *reinterpret_cast<__half2*>(&g_fh[oo+2]) = __halves2half2(h2,h3);
        *reinterpret_cast<__half2*>(&g_fl[oo])   = __halves2half2(l0,l1);
        *reinterpret_cast<__half2*>(&g_fl[oo+2]) = __halves2half2(l2,l3);
    }
}

// ---------------- deformable attention: warp per (b,g,pixel) --------------
__global__ void __launch_bounds__(256) attn_kernel()
{
    int warp = threadIdx.x >> 5, lane = threadIdx.x & 31;
    int px = blockIdx.x * 8 + warp;
    int g = blockIdx.y, b = blockIdx.z;
    int h = px >> 6, w = px & 63;

    const float* om = g_offmask + ((size_t)(b * HD + h) * WD + w) * NOP;
    float qv = g_q[((size_t)(b * HD + h) * WD + w) * CD + g * HCD + lane]
             * 0.17677669529663687f;

    float attn[KP], vk[KP];
#pragma unroll
    for (int k = 0; k < KP; k++) {
        float ox = om[g * 18 + 2 * k], oy = om[g * 18 + 2 * k + 1], mk = om[144 + k];
        float cx = fminf(fmaxf((float)w + ox, 0.f), (float)(WD - 1));
        float cy = fminf(fmaxf((float)h + oy, 0.f), (float)(HD - 1));
        float x0f = floorf(cx), y0f = floorf(cy);
        float fx = cx - x0f, fy = cy - y0f;
        int x0 = (int)x0f, y0 = (int)y0f;
        int x1 = min(x0 + 1, WD - 1), y1 = min(y0 + 1, HD - 1);
        size_t i00 = ((size_t)(b * HD + y0) * WD + x0) * CD + g * HCD + lane;
        size_t i01 = ((size_t)(b * HD + y0) * WD + x1) * CD + g * HCD + lane;
        size_t i10 = ((size_t)(b * HD + y1) * WD + x0) * CD + g * HCD + lane;
        size_t i11 = ((size_t)(b * HD + y1) * WD + x1) * CD + g * HCD + lane;
        float2 kv00 = g_kv[i00], kv01 = g_kv[i01];
        float2 kv10 = g_kv[i10], kv11 = g_kv[i11];
        float w00 = (1.f - fx) * (1.f - fy), w01 = fx * (1.f - fy);
        float w10 = (1.f - fx) * fy,         w11 = fx * fy;
        float kvv = kv00.x*w00 + kv01.x*w01 + kv10.x*w10 + kv11.x*w11;
        float vvv = kv00.y*w00 + kv01.y*w01 + kv10.y*w10 + kv11.y*w11;
        kvv *= mk; vvv *= mk;
        float d = qv * kvv;
#pragma unroll
        for (int s = 16; s; s >>= 1) d += __shfl_xor_sync(0xffffffffu, d, s);
        attn[k] = d;
        vk[k] = vvv;
    }
    float m = attn[0];
#pragma unroll
    for (int k = 1; k < KP; k++) m = fmaxf(m, attn[k]);
    float ssum = 0.f, o = 0.f;
#pragma unroll
    for (int k = 0; k < KP; k++) {
        float e = __expf(attn[k] - m);
        ssum += e;
        o += e * vk[k];
    }
    o /= ssum;
    size_t oi = ((size_t)((b * HD + h) * WD + w)) * CD + g * HCD + lane;
    __half hh, ll; split1(o, hh, ll);
    g_aoh[oi] = hh; g_aol[oi] = ll;
}

// --------------------------------- launch ---------------------------------
extern "C" void kernel_launch(void* const* d_in, const int* in_sizes, int n_in,
                              void* d_out, int out_size)
{
    const float* x            = (const float*)d_in[0];
    const float* qkv_w        = (const float*)d_in[1];
    const float* qkv_b        = (const float*)d_in[2];
    const float* dw_w         = (const float*)d_in[3];
    const float* dw_b         = (const float*)d_in[4];
    const float* off_pconv_w  = (const float*)d_in[5];
    const float* off_w        = (const float*)d_in[6];
    const float* off_b        = (const float*)d_in[7];
    const float* mask_pconv_w = (const float*)d_in[8];
    const float* mask_w       = (const float*)d_in[9];
    const float* mask_b       = (const float*)d_in[10];
    const float* proj_w       = (const float*)d_in[11];
    const float* proj_b       = (const float*)d_in[12];
    float* out = (float*)d_out;

    cudaFuncSetAttribute(gemm_kernel,
                         cudaFuncAttributeMaxDynamicSharedMemorySize, GEMM_SMEM);

    __half *xh, *xl, *qwh, *qwl, *pwh, *pwl, *cwh, *cwl, *fh, *fl, *aoh, *aol;
    float *qkv, *combB, *offmask;
    cudaGetSymbolAddress((void**)&xh, g_xhi);   cudaGetSymbolAddress((void**)&xl, g_xlo);
    cudaGetSymbolAddress((void**)&qwh, g_qwh);  cudaGetSymbolAddress((void**)&qwl, g_qwl);
    cudaGetSymbolAddress((void**)&pwh, g_pwh);  cudaGetSymbolAddress((void**)&pwl, g_pwl);
    cudaGetSymbolAddress((void**)&cwh, g_cwh);  cudaGetSymbolAddress((void**)&cwl, g_cwl);
    cudaGetSymbolAddress((void**)&fh, g_fh);    cudaGetSymbolAddress((void**)&fl, g_fl);
    cudaGetSymbolAddress((void**)&aoh, g_aoh);  cudaGetSymbolAddress((void**)&aol, g_aol);
    cudaGetSymbolAddress((void**)&qkv, g_qkv);
    cudaGetSymbolAddress((void**)&combB, g_combB);
    cudaGetSymbolAddress((void**)&offmask, g_offmask);

    // 0) conversions (merged) + weight folding
    convert_all_kernel<<<2048 + C3 + CD, 256>>>(x, qkv_w, proj_w);
    {
        dim3 grid(NOP, NF / 128);
        prep_kernel<<<grid, 128>>>(off_pconv_w, off_w, off_b,
                                   mask_pconv_w, mask_w, mask_b);
    }
    // 1) qkv GEMM: [8192,256] -> [8192,768]
    {
        dim3 grid(C3 / 64, MR / 128);
        gemm_kernel<<<grid, 256, GEMM_SMEM>>>(xh, xl, qwh, qwl, qkv_b, qkv, C3, CD);
    }
    // 2) depthwise conv -> g_q (fp32) + g_kv (float2 interleaved)
    {
        dim3 grid(WD / 4, HD, BD);
        dwconv_kernel<<<grid, 192>>>(qkv, dw_w, dw_b);
    }
    // 3) im2col features (from g_q)
    im2col_kernel<<<BD * HD, 256>>>();
    // 4) offset/mask GEMM: [8192,768] -> [8192,192]
    {
        dim3 grid(NOP / 64, MR / 128);
        gemm_kernel<<<grid, 256, GEMM_SMEM>>>(fh, fl, cwh, cwl, combB, offmask, NOP, NF);
    }
    // 5) attention
    {
        dim3 grid(PD / 8, GD, BD);
        attn_kernel<<<grid, 256>>>();
    }
    // 6) proj GEMM: [8192,256] -> [8192,256]
    {
        dim3 grid(CD / 64, MR / 128);
        gemm_kernel<<<grid, 256, GEMM_SMEM>>>(aoh, aol, pwh, pwl, proj_b, out, CD, CD);
    }
}